// round 5
// baseline (speedup 1.0000x reference)
#include <cuda_runtime.h>
#include <cstdint>
#include <math.h>

#define NIMG 16
#define NPROP 16384
#define NGT 128
#define M_TOT (NPROP + NGT)   // 16512
#define KPOS 128
#define KNEG 384
#define NSAMP 512
#define NC2 2048              // candidate buffer capacity

typedef unsigned long long ull;

// ---------------- scratch ----------------
__device__ unsigned g_rec[NIMG * M_TOT];    // (u23 << 1) | is_pos
__device__ int g_labcl[NIMG * M_TOT];       // label | (clamped_gt << 8)  (flagged only)

// ---------------- threefry2x32 (jax partitionable path) ----------------
__device__ __forceinline__ unsigned rscore_u(unsigned f) {
    unsigned k0 = 0u, k1 = 42u;
    unsigned ks2 = k0 ^ k1 ^ 0x1BD11BDAu;
    unsigned x0 = 0u, x1 = f;
    x0 += k0; x1 += k1;
#define TF_R(r) { x0 += x1; x1 = (x1 << (r)) | (x1 >> (32 - (r))); x1 ^= x0; }
    TF_R(13) TF_R(15) TF_R(26) TF_R(6)
    x0 += k1; x1 += ks2 + 1u;
    TF_R(17) TF_R(29) TF_R(16) TF_R(24)
    x0 += ks2; x1 += k0 + 2u;
    TF_R(13) TF_R(15) TF_R(26) TF_R(6)
    x0 += k0; x1 += k1 + 3u;
    TF_R(17) TF_R(29) TF_R(16) TF_R(24)
    x0 += k1; x1 += ks2 + 4u;
    TF_R(13) TF_R(15) TF_R(26) TF_R(6)
    x0 += ks2; x1 += k0 + 5u;
#undef TF_R
    return (x0 ^ x1) >> 9;   // 23-bit uniform; score = u * 2^-23 (monotone)
}

// ---------------- kernel A: windowed flag scan + rare exact redo ----------------
__global__ void __launch_bounds__(256) prep_kernel(
        const float4* __restrict__ proposals,
        const float4* __restrict__ gt_boxes,
        const int* __restrict__ gt_labels) {
    __shared__ float4 s_gt[NGT];     // original order (for redo + GT-proposal loads)
    __shared__ float  s_area[NGT];   // full areas (redo)
    __shared__ int    s_lab[NGT];
    __shared__ float4 s_sgt[NGT];    // sorted by x1 (flag scan)
    __shared__ float  s_sa3[NGT];    // area/3, sorted
    __shared__ float  s_sx1[NGT];    // x1, sorted
    __shared__ int    s_flag[1024];
    __shared__ int    s_nflag;

    const int i = blockIdx.y;
    const int t = threadIdx.x;
    if (t == 0) s_nflag = 0;
    if (t < NGT) {
        float4 g = gt_boxes[i * NGT + t];
        s_gt[t] = g;
        s_area[t] = __fmul_rn(__fsub_rn(g.z, g.x), __fsub_rn(g.w, g.y));
        s_lab[t] = gt_labels[i * NGT + t];
    }
    __syncthreads();
    if (t < NGT) {
        float gx = s_gt[t].x;
        int rank = 0;
        for (int j = 0; j < NGT; j++) {
            float oj = s_gt[j].x;
            rank += (oj < gx) || (oj == gx && j < t);
        }
        s_sgt[rank] = s_gt[t];
        s_sa3[rank] = s_area[t] * (1.0f / 3.0f);
        s_sx1[rank] = gx;
    }
    __syncthreads();

    const int gi = i * M_TOT;
    const int mb = blockIdx.x * 1024 + t * 4;
    unsigned rv[4];

    #pragma unroll
    for (int q = 0; q < 4; q++) {
        const int m = mb + q;
        if (m >= M_TOT) break;
        float4 p = (m < NPROP) ? proposals[(size_t)i * NPROP + m] : s_gt[m - NPROP];
        const float ab3 = __fmul_rn(__fmul_rn(__fsub_rn(p.z, p.x), __fsub_rn(p.w, p.y)),
                                    (1.0f / 3.0f));
        // window: GT widths <= 201 + eps  ->  x-overlap requires gx1 in [p.x-202, p.z]
        const float keylo = p.x - 202.0f;
        int l = 0, r = NGT;
        while (l < r) { int md = (l + r) >> 1; if (s_sx1[md] < keylo) l = md + 1; else r = md; }
        const int lo = l;
        r = NGT;
        while (l < r) { int md = (l + r) >> 1; if (s_sx1[md] <= p.z) l = md + 1; else r = md; }
        const int hi = l;

        float acc = -1e30f;
        for (int j = lo; j < hi; j++) {
            float4 g = s_sgt[j];
            float wx = __fsub_rn(fminf(g.z, p.z), fmaxf(g.x, p.x));
            float hy = __fsub_rn(fminf(g.w, p.w), fmaxf(g.y, p.y));
            float inter = __fmul_rn(fmaxf(wx, 0.0f), fmaxf(hy, 0.0f));
            acc = fmaxf(acc, __fsub_rn(inter, __fadd_rn(s_sa3[j], ab3)));
        }
        rv[q] = rscore_u((unsigned)(gi + m)) << 1;           // default: negative
        if (acc >= -1.0f) { int pp = atomicAdd(&s_nflag, 1); s_flag[pp] = m; }
    }
    if (mb + 3 < M_TOT) {
        *reinterpret_cast<uint4*>(&g_rec[gi + mb]) = make_uint4(rv[0], rv[1], rv[2], rv[3]);
    } else {
        for (int q = 0; q < 4; q++) if (mb + q < M_TOT) g_rec[gi + mb + q] = rv[q];
    }
    __syncthreads();

    // ---- exact redo: one warp per flagged proposal (validated path) ----
    const int nf = s_nflag;
    const int wid = t >> 5, lane = t & 31;
    for (int e = wid; e < nf; e += 8) {
        const int m = s_flag[e];
        float4 p = (m < NPROP) ? proposals[(size_t)i * NPROP + m] : s_gt[m - NPROP];
        const float ab = __fmul_rn(__fsub_rn(p.z, p.x), __fsub_rn(p.w, p.y));

        float bi, bd; int bj;
        {
            float4 g = s_gt[lane];
            float wx = __fsub_rn(fminf(g.z, p.z), fmaxf(g.x, p.x));
            float hy = __fsub_rn(fminf(g.w, p.w), fmaxf(g.y, p.y));
            bi = __fmul_rn(fmaxf(wx, 0.0f), fmaxf(hy, 0.0f));
            bd = __fsub_rn(__fadd_rn(s_area[lane], ab), bi);
            bj = lane;
        }
        #pragma unroll
        for (int kk = 1; kk < 4; kk++) {
            int j = lane + kk * 32;
            float4 g = s_gt[j];
            float wx = __fsub_rn(fminf(g.z, p.z), fmaxf(g.x, p.x));
            float hy = __fsub_rn(fminf(g.w, p.w), fmaxf(g.y, p.y));
            float inter = __fmul_rn(fmaxf(wx, 0.0f), fmaxf(hy, 0.0f));
            float den = __fsub_rn(__fadd_rn(s_area[j], ab), inter);
            float u = __fmul_rn(inter, bd), v = __fmul_rn(bi, den);
            float eu = __fmaf_rn(inter, bd, -u), ev = __fmaf_rn(bi, den, -v);
            if ((u > v) || (u == v && eu > ev)) { bi = inter; bd = den; bj = j; }
        }
        #pragma unroll
        for (int off = 16; off > 0; off >>= 1) {
            float obi = __shfl_xor_sync(0xFFFFFFFFu, bi, off);
            float obd = __shfl_xor_sync(0xFFFFFFFFu, bd, off);
            int   obj = __shfl_xor_sync(0xFFFFFFFFu, bj, off);
            float u = __fmul_rn(obi, bd), v = __fmul_rn(bi, obd);
            float eu = __fmaf_rn(obi, bd, -u), ev = __fmaf_rn(bi, obd, -v);
            bool gt = (u > v) || (u == v && eu > ev);
            bool eq = (u == v) && (eu == ev);
            if (gt || (eq && obj < bj)) { bi = obi; bd = obd; bj = obj; }
        }
        if (lane == 0) {
            bool pos = __fdiv_rn(bi, bd) >= 0.5f;     // bit-exact threshold
            int label = pos ? s_lab[bj] : 0;
            int cl = pos ? bj : 0;
            g_labcl[gi + m] = label | (cl << 8);
            g_rec[gi + m] = (rscore_u((unsigned)(gi + m)) << 1) | (pos ? 1u : 0u);
        }
    }
}

// ---------------- kernel B: atomic-free threshold + compaction + rank sort ----------------
__global__ void __launch_bounds__(1024) select_kernel(
        const float4* __restrict__ proposals,
        const float4* __restrict__ gt_boxes,
        float* __restrict__ out) {
    __shared__ ull cand[NC2];
    __shared__ int s_part[32];
    __shared__ int s_cnt, s_bcast;

    const int i = blockIdx.x;
    const int cat = blockIdx.y;            // 0 = pos, 1 = neg
    const unsigned want = cat ? 0u : 1u;
    const int k = cat ? KNEG : KPOS;
    const int t = threadIdx.x;
    const int lane = t & 31, wid = t >> 5;
    const unsigned* __restrict__ rec = g_rec + (size_t)i * M_TOT;

    // hold this thread's 17 records in registers
    unsigned uv[17]; bool cv[17];
    #pragma unroll
    for (int q = 0; q < 17; q++) {
        int m = t + q * 1024;
        unsigned r = (m < M_TOT) ? rec[m] : (want ^ 1u);
        cv[q] = ((r & 1u) == want);
        uv[q] = r >> 1;
    }

    // block-wide count of {category && u >= T}, zero atomics
    #define COUNT_T(T, RES) do {                                             \
        int _c = 0;                                                          \
        _Pragma("unroll")                                                    \
        for (int _q = 0; _q < 17; _q++) _c += (cv[_q] && uv[_q] >= (T));     \
        _Pragma("unroll")                                                    \
        for (int _o = 16; _o > 0; _o >>= 1)                                  \
            _c += __shfl_xor_sync(0xFFFFFFFFu, _c, _o);                      \
        if (lane == 0) s_part[wid] = _c;                                     \
        __syncthreads();                                                     \
        if (t == 0) { int _s = 0; for (int _w = 0; _w < 32; _w++) _s += s_part[_w]; s_bcast = _s; } \
        __syncthreads();                                                     \
        (RES) = s_bcast;                                                     \
        __syncthreads();                                                     \
    } while (0)

    // static guess (uniform order statistic, +-40 sigma margin); exact fallback
    unsigned T = cat ? 7978000u : 0u;
    int C;
    COUNT_T(T, C);
    if (C < k || C > NC2) {
        unsigned blo = 0, bhi = 8388607u;   // largest T with count >= k
        while (blo < bhi) {
            unsigned md = (blo + bhi + 1) >> 1;
            int c2; COUNT_T(md, c2);
            if (c2 >= k) blo = md; else bhi = md - 1;
        }
        T = blo;
        COUNT_T(T, C);
    }

    if (t == 0) s_cnt = 0;
    __syncthreads();

    // warp-aggregated compaction (1 atomic per warp per q)
    #pragma unroll
    for (int q = 0; q < 17; q++) {
        bool p = cv[q] && uv[q] >= T;
        unsigned mask = __ballot_sync(0xFFFFFFFFu, p);
        if (mask) {
            int leader = __ffs(mask) - 1;
            int base = 0;
            if (lane == leader) base = atomicAdd(&s_cnt, __popc(mask));
            base = __shfl_sync(0xFFFFFFFFu, base, leader);
            if (p) {
                int off = __popc(mask & ((1u << lane) - 1u));
                int m = t + q * 1024;
                int pos = base + off;
                if (pos < NC2)
                    cand[pos] = ((ull)uv[q] << 32) | (unsigned)(~(unsigned)m);
            }
        }
    }
    __syncthreads();
    const int CC = min(s_cnt, NC2);

    // rank-counting sort (distinct keys) + fused encode
    for (int c = t; c < CC; c += 1024) {
        const ull mykey = cand[c];
        int rnk = 0;
        for (int j = 0; j < CC; j++) rnk += (cand[j] > mykey);
        if (rnk < k) {
            int m = (int)(~(unsigned)(mykey & 0xFFFFFFFFULL));
            int label = 0, cl = 0;
            if (cat == 0) {
                int labcl = g_labcl[(size_t)i * M_TOT + m];
                label = labcl & 0xFF;
                cl = labcl >> 8;
            }
            float4 p = (m < NPROP) ? proposals[(size_t)i * NPROP + m]
                                   : gt_boxes[i * NGT + (m - NPROP)];
            float4 g = gt_boxes[i * NGT + cl];

            float rw = p.z - p.x, rh = p.w - p.y;
            float rcx = p.x + 0.5f * rw, rcy = p.y + 0.5f * rh;
            float gw = g.z - g.x, gh = g.w - g.y;
            float gcx = g.x + 0.5f * gw, gcy = g.y + 0.5f * gh;

            float t0 = 10.0f * __fdiv_rn(gcx - rcx, rw);
            float t1 = 10.0f * __fdiv_rn(gcy - rcy, rh);
            float t2 = 5.0f * logf(__fdiv_rn(gw, rw));
            float t3 = 5.0f * logf(__fdiv_rn(gh, rh));

            int row = i * NSAMP + (cat ? KPOS : 0) + rnk;
            out[row * 4 + 0] = t0;
            out[row * 4 + 1] = t1;
            out[row * 4 + 2] = t2;
            out[row * 4 + 3] = t3;
            out[NIMG * NSAMP * 4 + row] = (float)label;
            out[NIMG * NSAMP * 4 + NIMG * NSAMP + row] = (float)m;
        }
    }
}

// ---------------- launch ----------------
extern "C" void kernel_launch(void* const* d_in, const int* in_sizes, int n_in,
                              void* d_out, int out_size) {
    const float4* proposals = (const float4*)d_in[0];
    const float4* gt_boxes  = (const float4*)d_in[1];
    const int*    gt_labels = (const int*)d_in[2];
    float* out = (float*)d_out;

    prep_kernel<<<dim3((M_TOT + 1023) / 1024, NIMG), 256>>>(proposals, gt_boxes, gt_labels);
    select_kernel<<<dim3(NIMG, 2), 1024>>>(proposals, gt_boxes, out);
}

// round 6
// speedup vs baseline: 1.9698x; 1.9698x over previous
#include <cuda_runtime.h>
#include <cstdint>
#include <math.h>

#define NIMG 16
#define NPROP 16384
#define NGT 128
#define M_TOT (NPROP + NGT)   // 16512
#define KPOS 128
#define KNEG 384
#define NSAMP 512
#define NCAP 1536             // candidate buffer capacity

typedef unsigned long long ull;

// ---------------- scratch ----------------
__device__ unsigned g_rec[NIMG * M_TOT];    // (u23 << 1) | is_pos
__device__ int g_labcl[NIMG * M_TOT];       // label | (clamped_gt << 8)  (flagged only)

// ---------------- threefry2x32 (jax partitionable path) ----------------
__device__ __forceinline__ unsigned rscore_u(unsigned f) {
    unsigned k0 = 0u, k1 = 42u;
    unsigned ks2 = k0 ^ k1 ^ 0x1BD11BDAu;
    unsigned x0 = 0u, x1 = f;
    x0 += k0; x1 += k1;
#define TF_R(r) { x0 += x1; x1 = (x1 << (r)) | (x1 >> (32 - (r))); x1 ^= x0; }
    TF_R(13) TF_R(15) TF_R(26) TF_R(6)
    x0 += k1; x1 += ks2 + 1u;
    TF_R(17) TF_R(29) TF_R(16) TF_R(24)
    x0 += ks2; x1 += k0 + 2u;
    TF_R(13) TF_R(15) TF_R(26) TF_R(6)
    x0 += k0; x1 += k1 + 3u;
    TF_R(17) TF_R(29) TF_R(16) TF_R(24)
    x0 += k1; x1 += ks2 + 4u;
    TF_R(13) TF_R(15) TF_R(26) TF_R(6)
    x0 += ks2; x1 += k0 + 5u;
#undef TF_R
    return (x0 ^ x1) >> 9;   // 23-bit uniform; score = u * 2^-23 (monotone)
}

// ---------------- kernel A: LUT-windowed flag scan + rare exact redo ----------------
__global__ void __launch_bounds__(256) prep_kernel(
        const float4* __restrict__ proposals,
        const float4* __restrict__ gt_boxes,
        const int* __restrict__ gt_labels) {
    __shared__ float4 s_gt[NGT];     // original order (redo + GT-proposal loads)
    __shared__ float  s_area[NGT];   // full areas (redo)
    __shared__ int    s_lab[NGT];
    __shared__ float4 s_sgt[NGT];    // sorted by x1
    __shared__ float  s_sa3[NGT];    // area/3, sorted
    __shared__ int    s_lutlo[256];
    __shared__ int    s_luthi[256];
    __shared__ int    s_flag[1024];
    __shared__ int    s_nflag;

    const int i = blockIdx.y;
    const int t = threadIdx.x;
    if (t == 0) s_nflag = 0;
    if (t < NGT) {
        float4 g = gt_boxes[i * NGT + t];
        s_gt[t] = g;
        s_area[t] = __fmul_rn(__fsub_rn(g.z, g.x), __fsub_rn(g.w, g.y));
        s_lab[t] = gt_labels[i * NGT + t];
    }
    __syncthreads();
    if (t < NGT) {
        float gx = s_gt[t].x;
        int rank = 0;
        for (int j = 0; j < NGT; j++) {
            float oj = s_gt[j].x;
            rank += (oj < gx) || (oj == gx && j < t);
        }
        s_sgt[rank] = s_gt[t];
        s_sa3[rank] = s_area[t] * (1.0f / 3.0f);
    }
    __syncthreads();
    {   // bucket -> sorted-index LUT (conservative: superset window)
        const float vlo = t * (801.0f / 256.0f);
        const float vhi = (t + 1) * (801.0f / 256.0f);
        int clo = 0, chi = 0;
        for (int j = 0; j < NGT; j++) {
            float x = s_sgt[j].x;          // uniform j -> LDS broadcast
            clo += (x < vlo);
            chi += (x <= vhi);
        }
        s_lutlo[t] = clo;                  // first idx with x1 >= vlo
        s_luthi[t] = chi;                  // first idx with x1 >  vhi
    }
    __syncthreads();

    const int gi = i * M_TOT;
    const int mb = blockIdx.x * 1024 + t * 4;
    unsigned rv[4] = {0u, 0u, 0u, 0u};

    #pragma unroll
    for (int q = 0; q < 4; q++) {
        const int m = mb + q;
        if (m >= M_TOT) break;
        float4 p = (m < NPROP) ? proposals[(size_t)i * NPROP + m] : s_gt[m - NPROP];
        const float ab3 = __fmul_rn(__fmul_rn(__fsub_rn(p.z, p.x), __fsub_rn(p.w, p.y)),
                                    (1.0f / 3.0f));
        int lb = (int)((p.x - 202.0f) * (256.0f / 801.0f));
        lb = min(max(lb, 0), 255);
        int hb = (int)(p.z * (256.0f / 801.0f));
        hb = min(max(hb, 0), 255);
        const int lo = s_lutlo[lb];
        const int hi = s_luthi[hb];

        // flag iff possibly max-IoU >= 0.5:  inter - (area_g+area_b)/3 >= -1.0
        float acc = -1e30f;
        for (int j = lo; j < hi; j++) {
            float4 g = s_sgt[j];
            float wx = __fsub_rn(fminf(g.z, p.z), fmaxf(g.x, p.x));
            float hy = __fsub_rn(fminf(g.w, p.w), fmaxf(g.y, p.y));
            float inter = __fmul_rn(fmaxf(wx, 0.0f), fmaxf(hy, 0.0f));
            acc = fmaxf(acc, __fsub_rn(inter, __fadd_rn(s_sa3[j], ab3)));
        }
        rv[q] = rscore_u((unsigned)(gi + m)) << 1;           // default: negative
        if (acc >= -1.0f) { int pp = atomicAdd(&s_nflag, 1); s_flag[pp] = m; }
    }
    if (mb + 3 < M_TOT) {
        *reinterpret_cast<uint4*>(&g_rec[gi + mb]) = make_uint4(rv[0], rv[1], rv[2], rv[3]);
    } else {
        for (int q = 0; q < 4; q++) if (mb + q < M_TOT) g_rec[gi + mb + q] = rv[q];
    }
    __syncthreads();

    // ---- exact redo: one warp per flagged proposal (validated path) ----
    const int nf = s_nflag;
    const int wid = t >> 5, lane = t & 31;
    for (int e = wid; e < nf; e += 8) {
        const int m = s_flag[e];
        float4 p = (m < NPROP) ? proposals[(size_t)i * NPROP + m] : s_gt[m - NPROP];
        const float ab = __fmul_rn(__fsub_rn(p.z, p.x), __fsub_rn(p.w, p.y));

        float bi, bd; int bj;
        {
            float4 g = s_gt[lane];
            float wx = __fsub_rn(fminf(g.z, p.z), fmaxf(g.x, p.x));
            float hy = __fsub_rn(fminf(g.w, p.w), fmaxf(g.y, p.y));
            bi = __fmul_rn(fmaxf(wx, 0.0f), fmaxf(hy, 0.0f));
            bd = __fsub_rn(__fadd_rn(s_area[lane], ab), bi);
            bj = lane;
        }
        #pragma unroll
        for (int kk = 1; kk < 4; kk++) {
            int j = lane + kk * 32;
            float4 g = s_gt[j];
            float wx = __fsub_rn(fminf(g.z, p.z), fmaxf(g.x, p.x));
            float hy = __fsub_rn(fminf(g.w, p.w), fmaxf(g.y, p.y));
            float inter = __fmul_rn(fmaxf(wx, 0.0f), fmaxf(hy, 0.0f));
            float den = __fsub_rn(__fadd_rn(s_area[j], ab), inter);
            float u = __fmul_rn(inter, bd), v = __fmul_rn(bi, den);
            float eu = __fmaf_rn(inter, bd, -u), ev = __fmaf_rn(bi, den, -v);
            if ((u > v) || (u == v && eu > ev)) { bi = inter; bd = den; bj = j; }
        }
        #pragma unroll
        for (int off = 16; off > 0; off >>= 1) {
            float obi = __shfl_xor_sync(0xFFFFFFFFu, bi, off);
            float obd = __shfl_xor_sync(0xFFFFFFFFu, bd, off);
            int   obj = __shfl_xor_sync(0xFFFFFFFFu, bj, off);
            float u = __fmul_rn(obi, bd), v = __fmul_rn(bi, obd);
            float eu = __fmaf_rn(obi, bd, -u), ev = __fmaf_rn(bi, obd, -v);
            bool gt = (u > v) || (u == v && eu > ev);
            bool eq = (u == v) && (eu == ev);
            if (gt || (eq && obj < bj)) { bi = obi; bd = obd; bj = obj; }
        }
        if (lane == 0) {
            bool pos = __fdiv_rn(bi, bd) >= 0.5f;     // bit-exact threshold
            int label = pos ? s_lab[bj] : 0;
            int cl = pos ? bj : 0;
            g_labcl[gi + m] = label | (cl << 8);
            g_rec[gi + m] = (rscore_u((unsigned)(gi + m)) << 1) | (pos ? 1u : 0u);
        }
    }
}

// ---------------- kernel B: windowed histogram top-k + rank sort + encode ----------------
__global__ void __launch_bounds__(1024) select_kernel(
        const float4* __restrict__ proposals,
        const float4* __restrict__ gt_boxes,
        float* __restrict__ out) {
    __shared__ int hist[4096];
    __shared__ int csum[1024];
    __shared__ int c2[32];
    __shared__ ull cand[NCAP];
    __shared__ int s_part[32];
    __shared__ int s_cnt, s_B, s_w;

    const int i = blockIdx.x;
    const int cat = blockIdx.y;            // 0 = pos, 1 = neg
    const unsigned want = cat ? 0u : 1u;
    const int k = cat ? KNEG : KPOS;
    const int t = threadIdx.x;
    const int lane = t & 31, wid = t >> 5;
    const unsigned* __restrict__ rec = g_rec + (size_t)i * M_TOT;

    // this thread's 17 records in registers
    unsigned uv[17]; bool cv[17];
    #pragma unroll
    for (int q = 0; q < 17; q++) {
        int m = t + q * 1024;
        unsigned r = (m < M_TOT) ? rec[m] : (want ^ 1u);
        cv[q] = ((r & 1u) == want);
        uv[q] = r >> 1;
    }

    // window: neg starts at 2^23 - 2^19 (expected ~1016 >> k=384); pos = full range
    unsigned T_lo = cat ? (8388608u - 524288u) : 0u;
    int shift = cat ? 7 : 11;              // 4096 bins over the window

    {   // verify window count in [k, 4000]; widen if not (practically never)
        int c = 0;
        #pragma unroll
        for (int q = 0; q < 17; q++) c += (cv[q] && uv[q] >= T_lo);
        #pragma unroll
        for (int o = 16; o > 0; o >>= 1) c += __shfl_xor_sync(0xFFFFFFFFu, c, o);
        if (lane == 0) s_part[wid] = c;
        __syncthreads();
        if (t == 0) { int s = 0; for (int w = 0; w < 32; w++) s += s_part[w]; s_w = s; }
        __syncthreads();
        int Cw = s_w;
        if (Cw < k || Cw > 4000) { T_lo = 0u; shift = 11; }
    }
    __syncthreads();

    #pragma unroll
    for (int b = 0; b < 4; b++) hist[t + b * 1024] = 0;
    if (t == 0) s_cnt = 0;
    __syncthreads();

    // histogram ONLY windowed elements (~1000 atomics)
    #pragma unroll
    for (int q = 0; q < 17; q++)
        if (cv[q] && uv[q] >= T_lo) atomicAdd(&hist[(uv[q] - T_lo) >> shift], 1);
    __syncthreads();

    csum[t] = hist[t * 4] + hist[t * 4 + 1] + hist[t * 4 + 2] + hist[t * 4 + 3];
    __syncthreads();
    if (t < 32) {
        int s = 0;
        #pragma unroll
        for (int b = 0; b < 32; b++) s += csum[t * 32 + b];
        c2[t] = s;
    }
    __syncthreads();
    if (t == 0) {
        int acc = 0;
        int cc = 31;
        for (; cc > 0; cc--) { if (acc + c2[cc] >= k) break; acc += c2[cc]; }
        int tt = cc * 32 + 31;
        for (; tt > cc * 32; tt--) { if (acc + csum[tt] >= k) break; acc += csum[tt]; }
        int b = tt * 4 + 3;
        for (; b > tt * 4; b--) { if (acc + hist[b] >= k) break; acc += hist[b]; }
        s_B = b;
    }
    __syncthreads();
    const unsigned T = T_lo + ((unsigned)s_B << shift);   // CC = count(>=T) in [k, k+binload]

    // warp-aggregated compaction
    #pragma unroll
    for (int q = 0; q < 17; q++) {
        bool p = cv[q] && uv[q] >= T;
        unsigned mask = __ballot_sync(0xFFFFFFFFu, p);
        if (mask) {
            int leader = __ffs(mask) - 1;
            int base = 0;
            if (lane == leader) base = atomicAdd(&s_cnt, __popc(mask));
            base = __shfl_sync(0xFFFFFFFFu, base, leader);
            if (p) {
                int off = __popc(mask & ((1u << lane) - 1u));
                int pos = base + off;
                if (pos < NCAP)
                    cand[pos] = ((ull)uv[q] << 32) | (unsigned)(~(unsigned)(t + q * 1024));
            }
        }
    }
    __syncthreads();
    const int CC = min(s_cnt, NCAP);

    // rank-counting sort (distinct keys) + fused encode
    for (int c = t; c < CC; c += 1024) {
        const ull mykey = cand[c];
        int rnk = 0;
        for (int j = 0; j < CC; j++) rnk += (cand[j] > mykey);
        if (rnk < k) {
            int m = (int)(~(unsigned)(mykey & 0xFFFFFFFFULL));
            int label = 0, cl = 0;
            if (cat == 0) {
                int labcl = g_labcl[(size_t)i * M_TOT + m];
                label = labcl & 0xFF;
                cl = labcl >> 8;
            }
            float4 p = (m < NPROP) ? proposals[(size_t)i * NPROP + m]
                                   : gt_boxes[i * NGT + (m - NPROP)];
            float4 g = gt_boxes[i * NGT + cl];

            float rw = p.z - p.x, rh = p.w - p.y;
            float rcx = p.x + 0.5f * rw, rcy = p.y + 0.5f * rh;
            float gw = g.z - g.x, gh = g.w - g.y;
            float gcx = g.x + 0.5f * gw, gcy = g.y + 0.5f * gh;

            float t0 = 10.0f * __fdiv_rn(gcx - rcx, rw);
            float t1 = 10.0f * __fdiv_rn(gcy - rcy, rh);
            float t2 = 5.0f * logf(__fdiv_rn(gw, rw));
            float t3 = 5.0f * logf(__fdiv_rn(gh, rh));

            int row = i * NSAMP + (cat ? KPOS : 0) + rnk;
            out[row * 4 + 0] = t0;
            out[row * 4 + 1] = t1;
            out[row * 4 + 2] = t2;
            out[row * 4 + 3] = t3;
            out[NIMG * NSAMP * 4 + row] = (float)label;
            out[NIMG * NSAMP * 4 + NIMG * NSAMP + row] = (float)m;
        }
    }
}

// ---------------- launch ----------------
extern "C" void kernel_launch(void* const* d_in, const int* in_sizes, int n_in,
                              void* d_out, int out_size) {
    const float4* proposals = (const float4*)d_in[0];
    const float4* gt_boxes  = (const float4*)d_in[1];
    const int*    gt_labels = (const int*)d_in[2];
    float* out = (float*)d_out;

    prep_kernel<<<dim3((M_TOT + 1023) / 1024, NIMG), 256>>>(proposals, gt_boxes, gt_labels);
    select_kernel<<<dim3(NIMG, 2), 1024>>>(proposals, gt_boxes, out);
}